// round 13
// baseline (speedup 1.0000x reference)
#include <cuda_runtime.h>
#include <cuda_fp16.h>
#include <mma.h>
#include <math_constants.h>

using namespace nvcuda;

#define N_NODES 50000
#define N_EDGES 800000
#define IN_CH   64
#define HEADS   4
#define OUT_CH  64
#define HC      (HEADS * OUT_CH)   // 256
#define NEG_SLOPE 0.2f
#define NBLK_NODES 196             // ceil(50000/256)

#define GT_M    64                 // nodes per gemm block
#define W_COLS  272                // 256 xt cols + 8 logit cols + 8 pad
#define W_LD    280                // Ws smem leading dim (halves)
#define XA_LD   72                 // x tile leading dim (halves)
#define GEMM_THREADS 288           // 9 warps
#define NBLK_GEMM ((N_NODES + GT_M - 1) / GT_M)                       // 782
#define NBLK_COUNT ((N_EDGES / 4 + GEMM_THREADS - 1) / GEMM_THREADS)  // 695

// ---------------- device scratch ----------------
__device__ __align__(16) __half2 g_xth[(size_t)N_NODES * (HC / 2)]; // [N,128] fp16x2
__device__ __align__(16) __half  g_Wh[64 * W_COLS];                 // W'' fp16
__device__ __align__(16) float g_asrc[N_NODES * HEADS];
__device__ __align__(16) float g_adst[N_NODES * HEADS];
__device__ __align__(16) float4 g_w[N_EDGES];      // per-edge softmax numerators
__device__ int   g_count[N_NODES];
__device__ int   g_offs[N_NODES];
__device__ int   g_cursor[N_NODES];
__device__ int   g_esrc[N_EDGES];
__device__ unsigned long long g_state[NBLK_NODES]; // lookback: flag<<32 | value

__device__ __forceinline__ float leaky(float v) {
    return (v > 0.0f) ? v : NEG_SLOPE * v;
}

// ---------------- K0: prep — zero counts/state + build fp16 W'' ---------------
__global__ void prep_kernel(const float* __restrict__ W,
                            const float* __restrict__ att_src,
                            const float* __restrict__ att_dst) {
    int i = blockIdx.x * blockDim.x + threadIdx.x;
    if (i < N_NODES) g_count[i] = 0;
    if (i < NBLK_NODES) g_state[i] = 0ULL;
    if (i < 64 * W_COLS) {
        int k = i / W_COLS, c = i % W_COLS;
        float v;
        if (c < HC) {
            v = W[(size_t)k * HC + c];
        } else if (c < HC + 8) {
            int h = (c - HC) & 3;
            const float* av = (c < HC + 4) ? att_src : att_dst;
            float s = 0.0f;
            for (int t = 0; t < OUT_CH; t++)
                s += W[(size_t)k * HC + h * OUT_CH + t] * av[h * OUT_CH + t];
            v = s;
        } else {
            v = 0.0f;
        }
        g_Wh[i] = __float2half(v);
    }
}

// ---------------- K1 (fused): gemm blocks + count blocks in ONE launch --------
__global__ void __launch_bounds__(GEMM_THREADS, 4)
fused_gemm_count_kernel(const float* __restrict__ x, const int* __restrict__ ei) {
    __shared__ __align__(16) __half xa[GT_M * XA_LD];      // 9216 B
    __shared__ __align__(16) __half Ws[64 * W_LD];         // 35840 B
    __shared__ __align__(16) float  stage[9][16 * 16];     // 9216 B

    // ---- count branch ----
    if (blockIdx.x >= NBLK_GEMM) {
        int i = (blockIdx.x - NBLK_GEMM) * GEMM_THREADS + threadIdx.x;
        if (i < N_EDGES / 4) {
            int4 d = __ldg((const int4*)(ei + N_EDGES) + i);
            atomicAdd(&g_count[d.x], 1);
            atomicAdd(&g_count[d.y], 1);
            atomicAdd(&g_count[d.z], 1);
            atomicAdd(&g_count[d.w], 1);
        }
        return;
    }

    // ---- gemm branch ----
    const int tid  = threadIdx.x;
    const int warp = tid >> 5;
    const int lane = tid & 31;
    const int nblk = blockIdx.x * GT_M;

    for (int i = tid; i < GT_M * IN_CH; i += GEMM_THREADS) {
        int n = i >> 6, k = i & 63;
        int node = nblk + n;
        xa[n * XA_LD + k] = __float2half((node < N_NODES) ? x[(size_t)node * IN_CH + k] : 0.0f);
    }
    for (int i = tid; i < 64 * (W_COLS / 8); i += GEMM_THREADS) {
        int k = i / (W_COLS / 8), c8 = i % (W_COLS / 8);
        *(uint4*)(Ws + k * W_LD + c8 * 8) = __ldg((const uint4*)(g_Wh + k * W_COLS) + c8);
    }
    __syncthreads();

    const int  ct0  = (warp < 8) ? (2 * warp) : 16;
    const bool has2 = (warp < 8);
    const int  ct1  = ct0 + 1;

    wmma::fragment<wmma::matrix_b, 16, 16, 16, __half, wmma::row_major> b0[4], b1[4];
#pragma unroll
    for (int kk = 0; kk < 4; kk++) {
        wmma::load_matrix_sync(b0[kk], Ws + (kk * 16) * W_LD + ct0 * 16, W_LD);
        if (has2) wmma::load_matrix_sync(b1[kk], Ws + (kk * 16) * W_LD + ct1 * 16, W_LD);
    }

    float* st = stage[warp];
    __half* xth = (__half*)g_xth;

    auto emit = [&](int nt, int ct, wmma::fragment<wmma::accumulator, 16, 16, 16, float>& acc) {
        wmma::store_matrix_sync(st, acc, 16, wmma::mem_row_major);
        __syncwarp();
        if (ct < 16) {
            int row = lane & 15, ch = lane >> 4;
            int node = nblk + nt * 16 + row;
            if (node < N_NODES) {
                float4 u = *(const float4*)(st + row * 16 + ch * 8);
                float4 v = *(const float4*)(st + row * 16 + ch * 8 + 4);
                __half2 h0 = __floats2half2_rn(u.x, u.y);
                __half2 h1 = __floats2half2_rn(u.z, u.w);
                __half2 h2 = __floats2half2_rn(v.x, v.y);
                __half2 h3 = __floats2half2_rn(v.z, v.w);
                uint4 o = make_uint4(*(unsigned*)&h0, *(unsigned*)&h1,
                                     *(unsigned*)&h2, *(unsigned*)&h3);
                *(uint4*)(xth + (size_t)node * HC + ct * 16 + ch * 8) = o;
            }
        } else {
            if (lane < 16) {
                int node = nblk + nt * 16 + lane;
                if (node < N_NODES) {
                    *(float4*)(g_asrc + node * 4) = *(const float4*)(st + lane * 16);
                    *(float4*)(g_adst + node * 4) = *(const float4*)(st + lane * 16 + 4);
                }
            }
        }
        __syncwarp();
    };

#pragma unroll
    for (int nt = 0; nt < 4; nt++) {
        wmma::fragment<wmma::matrix_a, 16, 16, 16, __half, wmma::row_major> af;
        wmma::fragment<wmma::accumulator, 16, 16, 16, float> acc0, acc1;
        wmma::fill_fragment(acc0, 0.0f);
        if (has2) wmma::fill_fragment(acc1, 0.0f);
#pragma unroll
        for (int kk = 0; kk < 4; kk++) {
            wmma::load_matrix_sync(af, xa + (nt * 16) * XA_LD + kk * 16, XA_LD);
            wmma::mma_sync(acc0, af, b0[kk], acc0);
            if (has2) wmma::mma_sync(acc1, af, b1[kk], acc1);
        }
        emit(nt, ct0, acc0);
        if (has2) emit(nt, ct1, acc1);
    }
}

// ---------------- K2: single-kernel CSR scan (decoupled lookback) -------------
// 196 blocks x 256 threads; all co-resident (wave 1), so spins cannot deadlock.
// state word = flag<<32 | value; flag: 1 = aggregate ready, 2 = prefix ready.
__global__ void scan_kernel() {
    __shared__ int sm[256];
    __shared__ int s_excl;
    const int t = threadIdx.x;
    const int b = blockIdx.x;
    const int i = b * 256 + t;
    int c = (i < N_NODES) ? g_count[i] : 0;
    sm[t] = c;
    __syncthreads();
    for (int off = 1; off < 256; off <<= 1) {
        int u = (t >= off) ? sm[t - off] : 0;
        __syncthreads();
        sm[t] += u;
        __syncthreads();
    }
    int total = sm[255];

    if (t == 0) {
        if (b == 0) {
            atomicExch(&g_state[0], (2ULL << 32) | (unsigned)total);
            s_excl = 0;
        } else {
            atomicExch(&g_state[b], (1ULL << 32) | (unsigned)total);
            int excl = 0;
            int p = b - 1;
            while (true) {
                unsigned long long v = atomicAdd(&g_state[p], 0ULL);
                unsigned flag = (unsigned)(v >> 32);
                if (flag == 2u) { excl += (int)(unsigned)v; break; }
                if (flag == 1u) { excl += (int)(unsigned)v; p--; }
            }
            atomicExch(&g_state[b], (2ULL << 32) | (unsigned)(excl + total));
            s_excl = excl;
        }
    }
    __syncthreads();

    if (i < N_NODES) {
        int off = s_excl + sm[t] - c;
        g_offs[i] = off;
        g_cursor[i] = off;
    }
}

// ---------------- K3: scatter + edge-weight precompute (coalesced g_w) --------
__global__ void scatter_kernel(const int* __restrict__ ei) {
    int i = blockIdx.x * blockDim.x + threadIdx.x;
    if (i >= N_EDGES / 4) return;
    int4 s4 = __ldg((const int4*)ei + i);
    int4 d4 = __ldg((const int4*)(ei + N_EDGES) + i);
    int  sv[4] = {s4.x, s4.y, s4.z, s4.w};
    int  dv[4] = {d4.x, d4.y, d4.z, d4.w};
#pragma unroll
    for (int t = 0; t < 4; t++) {
        int src = sv[t], dst = dv[t];
        int pos = atomicAdd(&g_cursor[dst], 1);
        g_esrc[pos] = src;
        float4 as = *(const float4*)(g_asrc + src * 4);
        float4 ad = *(const float4*)(g_adst + dst * 4);
        float4 w;
        w.x = __expf(leaky(as.x + ad.x));
        w.y = __expf(leaky(as.y + ad.y));
        w.z = __expf(leaky(as.z + ad.z));
        w.w = __expf(leaky(as.w + ad.w));
        g_w[pos] = w;
    }
}

// ---------------- K4: agg — gather + head-mean + relu + fc (LDG.128 layout) ---
__global__ void agg_kernel(const float* __restrict__ bias,
                           const float* __restrict__ fc_w,
                           const float* __restrict__ fc_b,
                           float* __restrict__ out) {
    int i    = (blockIdx.x * blockDim.x + threadIdx.x) >> 5;
    int lane = threadIdx.x & 31;
    if (i >= N_NODES) return;

    const int h  = lane >> 3;
    const int cb = (lane & 7) * 8;
    const int start = g_offs[i];
    const int deg   = g_count[i];

    const float selfw = __expf(leaky(__ldg(g_asrc + 4 * i + h) + __ldg(g_adst + 4 * i + h)));
    const float* wflat = (const float*)g_w;

    float acc[8] = {0, 0, 0, 0, 0, 0, 0, 0};
    float s = 0.0f;

    int jn; float wn;
    if (deg > 0) { jn = __ldg(g_esrc + start); wn = __ldg(wflat + 4 * start + h); }
    else         { jn = i; wn = selfw; }

    for (int e = 0; e <= deg; e++) {
        int j = jn; float w = wn;
        int en = e + 1;
        if (en < deg)       { jn = __ldg(g_esrc + start + en); wn = __ldg(wflat + 4 * (start + en) + h); }
        else if (en == deg) { jn = i; wn = selfw; }

        s += w;
        uint4 v = __ldg((const uint4*)(g_xth + (size_t)j * (HC / 2)) + lane);
        float2 f0 = __half22float2(*(__half2*)&v.x);
        float2 f1 = __half22float2(*(__half2*)&v.y);
        float2 f2 = __half22float2(*(__half2*)&v.z);
        float2 f3 = __half22float2(*(__half2*)&v.w);
        acc[0] += w * f0.x; acc[1] += w * f0.y;
        acc[2] += w * f1.x; acc[3] += w * f1.y;
        acc[4] += w * f2.x; acc[5] += w * f2.y;
        acc[6] += w * f3.x; acc[7] += w * f3.y;
    }

    float inv = 0.25f / s;
#pragma unroll
    for (int c = 0; c < 8; c++) acc[c] *= inv;
#pragma unroll
    for (int c = 0; c < 8; c++) {
        acc[c] += __shfl_xor_sync(0xFFFFFFFFu, acc[c], 8);
        acc[c] += __shfl_xor_sync(0xFFFFFFFFu, acc[c], 16);
    }

    float4 b0 = __ldg((const float4*)(bias + cb));
    float4 b1 = __ldg((const float4*)(bias + cb + 4));
    float4 f0 = __ldg((const float4*)(fc_w + cb));
    float4 f1 = __ldg((const float4*)(fc_w + cb + 4));

    float p = fmaxf(acc[0] + b0.x, 0.0f) * f0.x
            + fmaxf(acc[1] + b0.y, 0.0f) * f0.y
            + fmaxf(acc[2] + b0.z, 0.0f) * f0.z
            + fmaxf(acc[3] + b0.w, 0.0f) * f0.w
            + fmaxf(acc[4] + b1.x, 0.0f) * f1.x
            + fmaxf(acc[5] + b1.y, 0.0f) * f1.y
            + fmaxf(acc[6] + b1.z, 0.0f) * f1.z
            + fmaxf(acc[7] + b1.w, 0.0f) * f1.w;

    p += __shfl_down_sync(0xFFFFFFFFu, p, 4, 8);
    p += __shfl_down_sync(0xFFFFFFFFu, p, 2, 8);
    p += __shfl_down_sync(0xFFFFFFFFu, p, 1, 8);

    if (lane == 0) out[i] = p + __ldg(fc_b);
}

// ---------------- launch (5 kernels; capture slot 3 = scatter) ----------------
extern "C" void kernel_launch(void* const* d_in, const int* in_sizes, int n_in,
                              void* d_out, int out_size) {
    const float* x        = (const float*)d_in[0];
    const int*   ei       = (const int*)d_in[1];     // int32 [2, E]
    const float* W        = (const float*)d_in[2];
    const float* att_src  = (const float*)d_in[3];
    const float* att_dst  = (const float*)d_in[4];
    const float* bias     = (const float*)d_in[5];
    const float* fc_w     = (const float*)d_in[6];
    const float* fc_b     = (const float*)d_in[7];
    float*       out      = (float*)d_out;

    (void)in_sizes; (void)n_in; (void)out_size;

    prep_kernel<<<NBLK_NODES, 256>>>(W, att_src, att_dst);
    fused_gemm_count_kernel<<<NBLK_GEMM + NBLK_COUNT, GEMM_THREADS>>>(x, ei);
    scan_kernel<<<NBLK_NODES, 256>>>();
    scatter_kernel<<<(N_EDGES / 4 + 255) / 256, 256>>>(ei);
    agg_kernel<<<(N_NODES * 32 + 255) / 256, 256>>>(bias, fc_w, fc_b, out);
}

// round 14
// speedup vs baseline: 1.0700x; 1.0700x over previous
#include <cuda_runtime.h>
#include <cuda_fp16.h>
#include <mma.h>
#include <math_constants.h>

using namespace nvcuda;

#define N_NODES 50000
#define N_EDGES 800000
#define IN_CH   64
#define HEADS   4
#define OUT_CH  64
#define HC      (HEADS * OUT_CH)   // 256
#define NEG_SLOPE 0.2f
#define NBLK_NODES 196             // ceil(50000/256)

#define GT_M    64                 // nodes per gemm block
#define W_COLS  272                // 256 xt cols + 8 logit cols + 8 pad
#define W_LD    280                // Ws smem leading dim (halves)
#define XA_LD   72                 // x tile leading dim (halves)
#define GEMM_THREADS 288           // 9 warps
#define NBLK_GEMM ((N_NODES + GT_M - 1) / GT_M)                       // 782
#define NBLK_COUNT ((N_EDGES / 4 + GEMM_THREADS - 1) / GEMM_THREADS)  // 695

// ---------------- device scratch ----------------
__device__ __align__(16) __half2 g_xth[(size_t)N_NODES * (HC / 2)]; // [N,128] fp16x2
__device__ __align__(16) __half  g_Wh[64 * W_COLS];                 // W'' fp16
__device__ __align__(16) float g_asrc[N_NODES * HEADS];
__device__ __align__(16) float g_adst[N_NODES * HEADS];
__device__ __align__(16) float4 g_w[N_EDGES];      // per-edge softmax numerators
__device__ int   g_count[N_NODES];
__device__ int   g_offs[N_NODES];
__device__ int   g_cursor[N_NODES];
__device__ int   g_esrc[N_EDGES];
__device__ unsigned long long g_state[NBLK_NODES]; // flag<<32 | value

__device__ __forceinline__ float leaky(float v) {
    return (v > 0.0f) ? v : NEG_SLOPE * v;
}

// ---------------- K0: prep — zero counts/state + build fp16 W'' ---------------
__global__ void prep_kernel(const float* __restrict__ W,
                            const float* __restrict__ att_src,
                            const float* __restrict__ att_dst) {
    int i = blockIdx.x * blockDim.x + threadIdx.x;
    if (i < N_NODES) g_count[i] = 0;
    if (i < NBLK_NODES) g_state[i] = 0ULL;
    if (i < 64 * W_COLS) {
        int k = i / W_COLS, c = i % W_COLS;
        float v;
        if (c < HC) {
            v = W[(size_t)k * HC + c];
        } else if (c < HC + 8) {
            int h = (c - HC) & 3;
            const float* av = (c < HC + 4) ? att_src : att_dst;
            float s = 0.0f;
            for (int t = 0; t < OUT_CH; t++)
                s += W[(size_t)k * HC + h * OUT_CH + t] * av[h * OUT_CH + t];
            v = s;
        } else {
            v = 0.0f;
        }
        g_Wh[i] = __float2half(v);
    }
}

// ---------------- K1 (fused): gemm blocks + count blocks in ONE launch --------
__global__ void __launch_bounds__(GEMM_THREADS, 4)
fused_gemm_count_kernel(const float* __restrict__ x, const int* __restrict__ ei) {
    __shared__ __align__(16) __half xa[GT_M * XA_LD];      // 9216 B
    __shared__ __align__(16) __half Ws[64 * W_LD];         // 35840 B
    __shared__ __align__(16) float  stage[9][16 * 16];     // 9216 B

    // ---- count branch ----
    if (blockIdx.x >= NBLK_GEMM) {
        int i = (blockIdx.x - NBLK_GEMM) * GEMM_THREADS + threadIdx.x;
        if (i < N_EDGES / 4) {
            int4 d = __ldg((const int4*)(ei + N_EDGES) + i);
            atomicAdd(&g_count[d.x], 1);
            atomicAdd(&g_count[d.y], 1);
            atomicAdd(&g_count[d.z], 1);
            atomicAdd(&g_count[d.w], 1);
        }
        return;
    }

    // ---- gemm branch ----
    const int tid  = threadIdx.x;
    const int warp = tid >> 5;
    const int lane = tid & 31;
    const int nblk = blockIdx.x * GT_M;

    for (int i = tid; i < GT_M * IN_CH; i += GEMM_THREADS) {
        int n = i >> 6, k = i & 63;
        int node = nblk + n;
        xa[n * XA_LD + k] = __float2half((node < N_NODES) ? x[(size_t)node * IN_CH + k] : 0.0f);
    }
    for (int i = tid; i < 64 * (W_COLS / 8); i += GEMM_THREADS) {
        int k = i / (W_COLS / 8), c8 = i % (W_COLS / 8);
        *(uint4*)(Ws + k * W_LD + c8 * 8) = __ldg((const uint4*)(g_Wh + k * W_COLS) + c8);
    }
    __syncthreads();

    const int  ct0  = (warp < 8) ? (2 * warp) : 16;
    const bool has2 = (warp < 8);
    const int  ct1  = ct0 + 1;

    wmma::fragment<wmma::matrix_b, 16, 16, 16, __half, wmma::row_major> b0[4], b1[4];
#pragma unroll
    for (int kk = 0; kk < 4; kk++) {
        wmma::load_matrix_sync(b0[kk], Ws + (kk * 16) * W_LD + ct0 * 16, W_LD);
        if (has2) wmma::load_matrix_sync(b1[kk], Ws + (kk * 16) * W_LD + ct1 * 16, W_LD);
    }

    float* st = stage[warp];
    __half* xth = (__half*)g_xth;

    auto emit = [&](int nt, int ct, wmma::fragment<wmma::accumulator, 16, 16, 16, float>& acc) {
        wmma::store_matrix_sync(st, acc, 16, wmma::mem_row_major);
        __syncwarp();
        if (ct < 16) {
            int row = lane & 15, ch = lane >> 4;
            int node = nblk + nt * 16 + row;
            if (node < N_NODES) {
                float4 u = *(const float4*)(st + row * 16 + ch * 8);
                float4 v = *(const float4*)(st + row * 16 + ch * 8 + 4);
                __half2 h0 = __floats2half2_rn(u.x, u.y);
                __half2 h1 = __floats2half2_rn(u.z, u.w);
                __half2 h2 = __floats2half2_rn(v.x, v.y);
                __half2 h3 = __floats2half2_rn(v.z, v.w);
                uint4 o = make_uint4(*(unsigned*)&h0, *(unsigned*)&h1,
                                     *(unsigned*)&h2, *(unsigned*)&h3);
                *(uint4*)(xth + (size_t)node * HC + ct * 16 + ch * 8) = o;
            }
        } else {
            if (lane < 16) {
                int node = nblk + nt * 16 + lane;
                if (node < N_NODES) {
                    *(float4*)(g_asrc + node * 4) = *(const float4*)(st + lane * 16);
                    *(float4*)(g_adst + node * 4) = *(const float4*)(st + lane * 16 + 4);
                }
            }
        }
        __syncwarp();
    };

#pragma unroll
    for (int nt = 0; nt < 4; nt++) {
        wmma::fragment<wmma::matrix_a, 16, 16, 16, __half, wmma::row_major> af;
        wmma::fragment<wmma::accumulator, 16, 16, 16, float> acc0, acc1;
        wmma::fill_fragment(acc0, 0.0f);
        if (has2) wmma::fill_fragment(acc1, 0.0f);
#pragma unroll
        for (int kk = 0; kk < 4; kk++) {
            wmma::load_matrix_sync(af, xa + (nt * 16) * XA_LD + kk * 16, XA_LD);
            wmma::mma_sync(acc0, af, b0[kk], acc0);
            if (has2) wmma::mma_sync(acc1, af, b1[kk], acc1);
        }
        emit(nt, ct0, acc0);
        if (has2) emit(nt, ct1, acc1);
    }
}

// ---------------- K2: single-pass CSR scan, central scanner -------------------
// All 196 blocks post aggregates (flag 1). Block 0's threads poll ALL slots in
// parallel, scan in smem, publish exclusive prefixes (flag 2). Each block polls
// only its own slot. All blocks co-resident (tiny footprint) -> no deadlock.
__global__ void scan_kernel() {
    __shared__ int sm[256];
    __shared__ int ag[256];
    __shared__ int s_excl;
    const int t = threadIdx.x;
    const int b = blockIdx.x;
    const int i = b * 256 + t;
    int c = (i < N_NODES) ? g_count[i] : 0;
    sm[t] = c;
    __syncthreads();
    for (int off = 1; off < 256; off <<= 1) {
        int u = (t >= off) ? sm[t - off] : 0;
        __syncthreads();
        sm[t] += u;
        __syncthreads();
    }

    if (t == 0)
        atomicExch(&g_state[b], (1ULL << 32) | (unsigned)sm[255]);
    __syncthreads();

    if (b == 0) {
        int a = 0;
        if (t < NBLK_NODES) {
            unsigned long long v;
            do { v = atomicAdd(&g_state[t], 0ULL); } while ((unsigned)(v >> 32) == 0u);
            a = (int)(unsigned)v;
        }
        ag[t] = a;
        __syncthreads();
        for (int off = 1; off < 256; off <<= 1) {
            int u = (t >= off) ? ag[t - off] : 0;
            __syncthreads();
            ag[t] += u;
            __syncthreads();
        }
        if (t < NBLK_NODES)
            atomicExch(&g_state[t], (2ULL << 32) | (unsigned)(ag[t] - a));
    }

    if (t == 0) {
        unsigned long long v;
        do { v = atomicAdd(&g_state[b], 0ULL); } while ((unsigned)(v >> 32) != 2u);
        s_excl = (int)(unsigned)v;
    }
    __syncthreads();

    if (i < N_NODES) {
        int off = s_excl + sm[t] - c;
        g_offs[i] = off;
        g_cursor[i] = off;
    }
}

// ---------------- K3: scatter — index-only dst sort ---------------------------
__global__ void scatter_kernel(const int* __restrict__ ei) {
    int i = blockIdx.x * blockDim.x + threadIdx.x;
    if (i >= N_EDGES / 4) return;
    int4 s4 = __ldg((const int4*)ei + i);
    int4 d4 = __ldg((const int4*)(ei + N_EDGES) + i);
    int p0 = atomicAdd(&g_cursor[d4.x], 1); g_esrc[p0] = s4.x;
    int p1 = atomicAdd(&g_cursor[d4.y], 1); g_esrc[p1] = s4.y;
    int p2 = atomicAdd(&g_cursor[d4.z], 1); g_esrc[p2] = s4.z;
    int p3 = atomicAdd(&g_cursor[d4.w], 1); g_esrc[p3] = s4.w;
}

// ---------------- K4: per-edge softmax numerators (coalesced writes) ----------
// one warp per dst node; lanes stride the node's contiguous edge range.
__global__ void weight_kernel() {
    int i    = (blockIdx.x * blockDim.x + threadIdx.x) >> 5;
    int lane = threadIdx.x & 31;
    if (i >= N_NODES) return;
    const int start = g_offs[i];
    const int deg   = g_count[i];
    float4 ad = *(const float4*)(g_adst + 4 * i);
    for (int e = start + lane; e < start + deg; e += 32) {
        int j = __ldg(g_esrc + e);
        float4 as = *(const float4*)(g_asrc + 4 * j);
        float4 w;
        w.x = __expf(leaky(as.x + ad.x));
        w.y = __expf(leaky(as.y + ad.y));
        w.z = __expf(leaky(as.z + ad.z));
        w.w = __expf(leaky(as.w + ad.w));
        g_w[e] = w;
    }
}

// ---------------- K5: agg — gather + head-mean + relu + fc (LDG.128 layout) ---
__global__ void agg_kernel(const float* __restrict__ bias,
                           const float* __restrict__ fc_w,
                           const float* __restrict__ fc_b,
                           float* __restrict__ out) {
    int i    = (blockIdx.x * blockDim.x + threadIdx.x) >> 5;
    int lane = threadIdx.x & 31;
    if (i >= N_NODES) return;

    const int h  = lane >> 3;
    const int cb = (lane & 7) * 8;
    const int start = g_offs[i];
    const int deg   = g_count[i];

    const float selfw = __expf(leaky(__ldg(g_asrc + 4 * i + h) + __ldg(g_adst + 4 * i + h)));
    const float* wflat = (const float*)g_w;

    float acc[8] = {0, 0, 0, 0, 0, 0, 0, 0};
    float s = 0.0f;

    int jn; float wn;
    if (deg > 0) { jn = __ldg(g_esrc + start); wn = __ldg(wflat + 4 * start + h); }
    else         { jn = i; wn = selfw; }

    for (int e = 0; e <= deg; e++) {
        int j = jn; float w = wn;
        int en = e + 1;
        if (en < deg)       { jn = __ldg(g_esrc + start + en); wn = __ldg(wflat + 4 * (start + en) + h); }
        else if (en == deg) { jn = i; wn = selfw; }

        s += w;
        uint4 v = __ldg((const uint4*)(g_xth + (size_t)j * (HC / 2)) + lane);
        float2 f0 = __half22float2(*(__half2*)&v.x);
        float2 f1 = __half22float2(*(__half2*)&v.y);
        float2 f2 = __half22float2(*(__half2*)&v.z);
        float2 f3 = __half22float2(*(__half2*)&v.w);
        acc[0] += w * f0.x; acc[1] += w * f0.y;
        acc[2] += w * f1.x; acc[3] += w * f1.y;
        acc[4] += w * f2.x; acc[5] += w * f2.y;
        acc[6] += w * f3.x; acc[7] += w * f3.y;
    }

    float inv = 0.25f / s;
#pragma unroll
    for (int c = 0; c < 8; c++) acc[c] *= inv;
#pragma unroll
    for (int c = 0; c < 8; c++) {
        acc[c] += __shfl_xor_sync(0xFFFFFFFFu, acc[c], 8);
        acc[c] += __shfl_xor_sync(0xFFFFFFFFu, acc[c], 16);
    }

    float4 b0 = __ldg((const float4*)(bias + cb));
    float4 b1 = __ldg((const float4*)(bias + cb + 4));
    float4 f0 = __ldg((const float4*)(fc_w + cb));
    float4 f1 = __ldg((const float4*)(fc_w + cb + 4));

    float p = fmaxf(acc[0] + b0.x, 0.0f) * f0.x
            + fmaxf(acc[1] + b0.y, 0.0f) * f0.y
            + fmaxf(acc[2] + b0.z, 0.0f) * f0.z
            + fmaxf(acc[3] + b0.w, 0.0f) * f0.w
            + fmaxf(acc[4] + b1.x, 0.0f) * f1.x
            + fmaxf(acc[5] + b1.y, 0.0f) * f1.y
            + fmaxf(acc[6] + b1.z, 0.0f) * f1.z
            + fmaxf(acc[7] + b1.w, 0.0f) * f1.w;

    p += __shfl_down_sync(0xFFFFFFFFu, p, 4, 8);
    p += __shfl_down_sync(0xFFFFFFFFu, p, 2, 8);
    p += __shfl_down_sync(0xFFFFFFFFu, p, 1, 8);

    if (lane == 0) out[i] = p + __ldg(fc_b);
}

// ---------------- launch (6 kernels; capture slot 3 = slim scatter) -----------
extern "C" void kernel_launch(void* const* d_in, const int* in_sizes, int n_in,
                              void* d_out, int out_size) {
    const float* x        = (const float*)d_in[0];
    const int*   ei       = (const int*)d_in[1];     // int32 [2, E]
    const float* W        = (const float*)d_in[2];
    const float* att_src  = (const float*)d_in[3];
    const float* att_dst  = (const float*)d_in[4];
    const float* bias     = (const float*)d_in[5];
    const float* fc_w     = (const float*)d_in[6];
    const float* fc_b     = (const float*)d_in[7];
    float*       out      = (float*)d_out;

    (void)in_sizes; (void)n_in; (void)out_size;

    prep_kernel<<<NBLK_NODES, 256>>>(W, att_src, att_dst);
    fused_gemm_count_kernel<<<NBLK_GEMM + NBLK_COUNT, GEMM_THREADS>>>(x, ei);
    scan_kernel<<<NBLK_NODES, 256>>>();
    scatter_kernel<<<(N_EDGES / 4 + 255) / 256, 256>>>(ei);
    weight_kernel<<<(N_NODES * 32 + 255) / 256, 256>>>();
    agg_kernel<<<(N_NODES * 32 + 255) / 256, 256>>>(bias, fc_w, fc_b, out);
}

// round 15
// speedup vs baseline: 1.0743x; 1.0040x over previous
#include <cuda_runtime.h>
#include <cuda_fp16.h>
#include <mma.h>
#include <math_constants.h>

using namespace nvcuda;

#define N_NODES 50000
#define N_EDGES 800000
#define IN_CH   64
#define HEADS   4
#define OUT_CH  64
#define HC      (HEADS * OUT_CH)   // 256
#define NEG_SLOPE 0.2f
#define NBLK_NODES 196             // ceil(50000/256)

#define GT_M    64                 // nodes per gemm block
#define W_COLS  272                // 256 xt cols + 8 logit cols + 8 pad
#define W_LD    280                // Ws smem leading dim (halves)
#define XA_LD   72                 // x tile leading dim (halves)
#define GEMM_THREADS 288           // 9 warps
#define NBLK_GEMM ((N_NODES + GT_M - 1) / GT_M)                       // 782
#define NBLK_COUNT ((N_EDGES / 4 + GEMM_THREADS - 1) / GEMM_THREADS)  // 695

// ---------------- device scratch ----------------
__device__ __align__(16) __half2 g_xth[(size_t)N_NODES * (HC / 2)]; // [N,128] fp16x2
__device__ __align__(16) __half  g_Wh[64 * W_COLS];                 // W'' fp16
__device__ __align__(16) float g_asrc[N_NODES * HEADS];
__device__ __align__(16) float g_adst[N_NODES * HEADS];
__device__ __align__(16) float4 g_w[N_EDGES];      // per-edge softmax numerators
__device__ int   g_count[N_NODES];
__device__ int   g_offs[N_NODES];
__device__ int   g_cursor[N_NODES];
__device__ int   g_esrc[N_EDGES];
__device__ unsigned long long g_state[NBLK_NODES]; // flag<<32 | value

__device__ __forceinline__ float leaky(float v) {
    return (v > 0.0f) ? v : NEG_SLOPE * v;
}

// ---------------- K0: prep — zero counts/state + build fp16 W'' ---------------
__global__ void prep_kernel(const float* __restrict__ W,
                            const float* __restrict__ att_src,
                            const float* __restrict__ att_dst) {
    int i = blockIdx.x * blockDim.x + threadIdx.x;
    if (i < N_NODES) g_count[i] = 0;
    if (i < NBLK_NODES) g_state[i] = 0ULL;
    if (i < 64 * W_COLS) {
        int k = i / W_COLS, c = i % W_COLS;
        float v;
        if (c < HC) {
            v = W[(size_t)k * HC + c];
        } else if (c < HC + 8) {
            int h = (c - HC) & 3;
            const float* av = (c < HC + 4) ? att_src : att_dst;
            float s = 0.0f;
            for (int t = 0; t < OUT_CH; t++)
                s += W[(size_t)k * HC + h * OUT_CH + t] * av[h * OUT_CH + t];
            v = s;
        } else {
            v = 0.0f;
        }
        g_Wh[i] = __float2half(v);
    }
}

// ---------------- K1 (fused): gemm blocks + count blocks in ONE launch --------
__global__ void __launch_bounds__(GEMM_THREADS, 4)
fused_gemm_count_kernel(const float* __restrict__ x, const int* __restrict__ ei) {
    __shared__ __align__(16) __half xa[GT_M * XA_LD];      // 9216 B
    __shared__ __align__(16) __half Ws[64 * W_LD];         // 35840 B
    __shared__ __align__(16) float  stage[9][16 * 16];     // 9216 B

    // ---- count branch ----
    if (blockIdx.x >= NBLK_GEMM) {
        int i = (blockIdx.x - NBLK_GEMM) * GEMM_THREADS + threadIdx.x;
        if (i < N_EDGES / 4) {
            int4 d = __ldg((const int4*)(ei + N_EDGES) + i);
            atomicAdd(&g_count[d.x], 1);
            atomicAdd(&g_count[d.y], 1);
            atomicAdd(&g_count[d.z], 1);
            atomicAdd(&g_count[d.w], 1);
        }
        return;
    }

    // ---- gemm branch ----
    const int tid  = threadIdx.x;
    const int warp = tid >> 5;
    const int lane = tid & 31;
    const int nblk = blockIdx.x * GT_M;

    for (int i = tid; i < GT_M * IN_CH; i += GEMM_THREADS) {
        int n = i >> 6, k = i & 63;
        int node = nblk + n;
        xa[n * XA_LD + k] = __float2half((node < N_NODES) ? x[(size_t)node * IN_CH + k] : 0.0f);
    }
    for (int i = tid; i < 64 * (W_COLS / 8); i += GEMM_THREADS) {
        int k = i / (W_COLS / 8), c8 = i % (W_COLS / 8);
        *(uint4*)(Ws + k * W_LD + c8 * 8) = __ldg((const uint4*)(g_Wh + k * W_COLS) + c8);
    }
    __syncthreads();

    const int  ct0  = (warp < 8) ? (2 * warp) : 16;
    const bool has2 = (warp < 8);
    const int  ct1  = ct0 + 1;

    wmma::fragment<wmma::matrix_b, 16, 16, 16, __half, wmma::row_major> b0[4], b1[4];
#pragma unroll
    for (int kk = 0; kk < 4; kk++) {
        wmma::load_matrix_sync(b0[kk], Ws + (kk * 16) * W_LD + ct0 * 16, W_LD);
        if (has2) wmma::load_matrix_sync(b1[kk], Ws + (kk * 16) * W_LD + ct1 * 16, W_LD);
    }

    float* st = stage[warp];
    __half* xth = (__half*)g_xth;

    auto emit = [&](int nt, int ct, wmma::fragment<wmma::accumulator, 16, 16, 16, float>& acc) {
        wmma::store_matrix_sync(st, acc, 16, wmma::mem_row_major);
        __syncwarp();
        if (ct < 16) {
            int row = lane & 15, ch = lane >> 4;
            int node = nblk + nt * 16 + row;
            if (node < N_NODES) {
                float4 u = *(const float4*)(st + row * 16 + ch * 8);
                float4 v = *(const float4*)(st + row * 16 + ch * 8 + 4);
                __half2 h0 = __floats2half2_rn(u.x, u.y);
                __half2 h1 = __floats2half2_rn(u.z, u.w);
                __half2 h2 = __floats2half2_rn(v.x, v.y);
                __half2 h3 = __floats2half2_rn(v.z, v.w);
                uint4 o = make_uint4(*(unsigned*)&h0, *(unsigned*)&h1,
                                     *(unsigned*)&h2, *(unsigned*)&h3);
                *(uint4*)(xth + (size_t)node * HC + ct * 16 + ch * 8) = o;
            }
        } else {
            if (lane < 16) {
                int node = nblk + nt * 16 + lane;
                if (node < N_NODES) {
                    *(float4*)(g_asrc + node * 4) = *(const float4*)(st + lane * 16);
                    *(float4*)(g_adst + node * 4) = *(const float4*)(st + lane * 16 + 4);
                }
            }
        }
        __syncwarp();
    };

#pragma unroll
    for (int nt = 0; nt < 4; nt++) {
        wmma::fragment<wmma::matrix_a, 16, 16, 16, __half, wmma::row_major> af;
        wmma::fragment<wmma::accumulator, 16, 16, 16, float> acc0, acc1;
        wmma::fill_fragment(acc0, 0.0f);
        if (has2) wmma::fill_fragment(acc1, 0.0f);
#pragma unroll
        for (int kk = 0; kk < 4; kk++) {
            wmma::load_matrix_sync(af, xa + (nt * 16) * XA_LD + kk * 16, XA_LD);
            wmma::mma_sync(acc0, af, b0[kk], acc0);
            if (has2) wmma::mma_sync(acc1, af, b1[kk], acc1);
        }
        emit(nt, ct0, acc0);
        if (has2) emit(nt, ct1, acc1);
    }
}

// ---------------- K2: single-pass CSR scan, central scanner -------------------
__global__ void scan_kernel() {
    __shared__ int sm[256];
    __shared__ int ag[256];
    __shared__ int s_excl;
    const int t = threadIdx.x;
    const int b = blockIdx.x;
    const int i = b * 256 + t;
    int c = (i < N_NODES) ? g_count[i] : 0;
    sm[t] = c;
    __syncthreads();
    for (int off = 1; off < 256; off <<= 1) {
        int u = (t >= off) ? sm[t - off] : 0;
        __syncthreads();
        sm[t] += u;
        __syncthreads();
    }

    if (t == 0)
        atomicExch(&g_state[b], (1ULL << 32) | (unsigned)sm[255]);
    __syncthreads();

    if (b == 0) {
        int a = 0;
        if (t < NBLK_NODES) {
            unsigned long long v;
            do { v = atomicAdd(&g_state[t], 0ULL); } while ((unsigned)(v >> 32) == 0u);
            a = (int)(unsigned)v;
        }
        ag[t] = a;
        __syncthreads();
        for (int off = 1; off < 256; off <<= 1) {
            int u = (t >= off) ? ag[t - off] : 0;
            __syncthreads();
            ag[t] += u;
            __syncthreads();
        }
        if (t < NBLK_NODES)
            atomicExch(&g_state[t], (2ULL << 32) | (unsigned)(ag[t] - a));
    }

    if (t == 0) {
        unsigned long long v;
        do { v = atomicAdd(&g_state[b], 0ULL); } while ((unsigned)(v >> 32) != 2u);
        s_excl = (int)(unsigned)v;
    }
    __syncthreads();

    if (i < N_NODES) {
        int off = s_excl + sm[t] - c;
        g_offs[i] = off;
        g_cursor[i] = off;
    }
}

// ---------------- K3: scatter — index-only dst sort, 8 edges/thread -----------
__global__ void scatter_kernel(const int* __restrict__ ei) {
    int i = blockIdx.x * blockDim.x + threadIdx.x;
    if (i >= N_EDGES / 8) return;
    int4 sa = __ldg((const int4*)ei + 2 * i);
    int4 sb = __ldg((const int4*)ei + 2 * i + 1);
    int4 da = __ldg((const int4*)(ei + N_EDGES) + 2 * i);
    int4 db = __ldg((const int4*)(ei + N_EDGES) + 2 * i + 1);
    int p0 = atomicAdd(&g_cursor[da.x], 1);
    int p1 = atomicAdd(&g_cursor[da.y], 1);
    int p2 = atomicAdd(&g_cursor[da.z], 1);
    int p3 = atomicAdd(&g_cursor[da.w], 1);
    int p4 = atomicAdd(&g_cursor[db.x], 1);
    int p5 = atomicAdd(&g_cursor[db.y], 1);
    int p6 = atomicAdd(&g_cursor[db.z], 1);
    int p7 = atomicAdd(&g_cursor[db.w], 1);
    g_esrc[p0] = sa.x; g_esrc[p1] = sa.y; g_esrc[p2] = sa.z; g_esrc[p3] = sa.w;
    g_esrc[p4] = sb.x; g_esrc[p5] = sb.y; g_esrc[p6] = sb.z; g_esrc[p7] = sb.w;
}

// ---------------- K4: per-edge softmax numerators — 8 lanes per node ----------
__global__ void weight_kernel() {
    int gid  = blockIdx.x * blockDim.x + threadIdx.x;
    int i    = gid >> 3;               // node
    int sub  = gid & 7;
    if (i >= N_NODES) return;
    const int start = g_offs[i];
    const int deg   = g_count[i];
    float4 ad = *(const float4*)(g_adst + 4 * i);
    for (int e = start + sub; e < start + deg; e += 8) {
        int j = __ldg(g_esrc + e);
        float4 as = *(const float4*)(g_asrc + 4 * j);
        float4 w;
        w.x = __expf(leaky(as.x + ad.x));
        w.y = __expf(leaky(as.y + ad.y));
        w.z = __expf(leaky(as.z + ad.z));
        w.w = __expf(leaky(as.w + ad.w));
        g_w[e] = w;
    }
}

// ---------------- K5: agg — gather + head-mean + relu + fc, unroll-by-2 -------
// one warp per dst node. lane owns bytes [16*lane,16*lane+16) of the 512B row:
// 8 channels of head (lane>>3), channel-in-head base cb=(lane&7)*8.
__global__ void agg_kernel(const float* __restrict__ bias,
                           const float* __restrict__ fc_w,
                           const float* __restrict__ fc_b,
                           float* __restrict__ out) {
    int i    = (blockIdx.x * blockDim.x + threadIdx.x) >> 5;
    int lane = threadIdx.x & 31;
    if (i >= N_NODES) return;

    const int h  = lane >> 3;
    const int cb = (lane & 7) * 8;
    const int start = g_offs[i];
    const int deg   = g_count[i];

    const float selfw = __expf(leaky(__ldg(g_asrc + 4 * i + h) + __ldg(g_adst + 4 * i + h)));
    const float* wflat = (const float*)g_w;

    float acc[8] = {0, 0, 0, 0, 0, 0, 0, 0};
    float s = 0.0f;

    auto accum = [&](float w, const uint4& v) {
        s += w;
        float2 f0 = __half22float2(*(__half2*)&v.x);
        float2 f1 = __half22float2(*(__half2*)&v.y);
        float2 f2 = __half22float2(*(__half2*)&v.z);
        float2 f3 = __half22float2(*(__half2*)&v.w);
        acc[0] += w * f0.x; acc[1] += w * f0.y;
        acc[2] += w * f1.x; acc[3] += w * f1.y;
        acc[4] += w * f2.x; acc[5] += w * f2.y;
        acc[6] += w * f3.x; acc[7] += w * f3.y;
    };

    const int total = deg + 1;   // edges + self-loop
    int e = 0;
    for (; e + 1 < total; e += 2) {
        // fetch indices/weights for a PAIR, then issue both row gathers together
        int   ja = (e     < deg) ? __ldg(g_esrc + start + e)     : i;
        int   jb = (e + 1 < deg) ? __ldg(g_esrc + start + e + 1) : i;
        float wa = (e     < deg) ? __ldg(wflat + 4 * (start + e) + h)     : selfw;
        float wb = (e + 1 < deg) ? __ldg(wflat + 4 * (start + e + 1) + h) : selfw;
        uint4 va = __ldg((const uint4*)(g_xth + (size_t)ja * (HC / 2)) + lane);
        uint4 vb = __ldg((const uint4*)(g_xth + (size_t)jb * (HC / 2)) + lane);
        accum(wa, va);
        accum(wb, vb);
    }
    if (e < total) {
        int   j = (e < deg) ? __ldg(g_esrc + start + e) : i;
        float w = (e < deg) ? __ldg(wflat + 4 * (start + e) + h) : selfw;
        uint4 v = __ldg((const uint4*)(g_xth + (size_t)j * (HC / 2)) + lane);
        accum(w, v);
    }

    float inv = 0.25f / s;
#pragma unroll
    for (int c = 0; c < 8; c++) acc[c] *= inv;
#pragma unroll
    for (int c = 0; c < 8; c++) {
        acc[c] += __shfl_xor_sync(0xFFFFFFFFu, acc[c], 8);
        acc[c] += __shfl_xor_sync(0xFFFFFFFFu, acc[c], 16);
    }

    float4 b0 = __ldg((const float4*)(bias + cb));
    float4 b1 = __ldg((const float4*)(bias + cb + 4));
    float4 f0 = __ldg((const float4*)(fc_w + cb));
    float4 f1 = __ldg((const float4*)(fc_w + cb + 4));

    float p = fmaxf(acc[0] + b0.x, 0.0f) * f0.x
            + fmaxf(acc[1] + b0.y, 0.0f) * f0.y
            + fmaxf(acc[2] + b0.z, 0.0f) * f0.z
            + fmaxf(acc[3] + b0.w, 0.0f) * f0.w
            + fmaxf(acc[4] + b1.x, 0.0f) * f1.x
            + fmaxf(acc[5] + b1.y, 0.0f) * f1.y
            + fmaxf(acc[6] + b1.z, 0.0f) * f1.z
            + fmaxf(acc[7] + b1.w, 0.0f) * f1.w;

    p += __shfl_down_sync(0xFFFFFFFFu, p, 4, 8);
    p += __shfl_down_sync(0xFFFFFFFFu, p, 2, 8);
    p += __shfl_down_sync(0xFFFFFFFFu, p, 1, 8);

    if (lane == 0) out[i] = p + __ldg(fc_b);
}

// ---------------- launch ----------------
extern "C" void kernel_launch(void* const* d_in, const int* in_sizes, int n_in,
                              void* d_out, int out_size) {
    const float* x        = (const float*)d_in[0];
    const int*   ei       = (const int*)d_in[1];     // int32 [2, E]
    const float* W        = (const float*)d_in[2];
    const float* att_src  = (const float*)d_in[3];
    const float* att_dst  = (const float*)d_in[4];
    const float* bias     = (const float*)d_in[5];
    const float* fc_w     = (const float*)d_in[6];
    const float* fc_b     = (const float*)d_in[7];
    float*       out      = (float*)d_out;

    (void)in_sizes; (void)n_in; (void)out_size;

    prep_kernel<<<NBLK_NODES, 256>>>(W, att_src, att_dst);
    fused_gemm_count_kernel<<<NBLK_GEMM + NBLK_COUNT, GEMM_THREADS>>>(x, ei);
    scan_kernel<<<NBLK_NODES, 256>>>();
    scatter_kernel<<<(N_EDGES / 8 + 255) / 256, 256>>>(ei);
    weight_kernel<<<(N_NODES * 8 + 255) / 256, 256>>>();
    agg_kernel<<<(N_NODES * 32 + 255) / 256, 256>>>(bias, fc_w, fc_b, out);
}

// round 16
// speedup vs baseline: 1.1116x; 1.0347x over previous
#include <cuda_runtime.h>
#include <cuda_fp16.h>
#include <mma.h>
#include <math_constants.h>

using namespace nvcuda;

#define N_NODES 50000
#define N_EDGES 800000
#define IN_CH   64
#define HEADS   4
#define OUT_CH  64
#define HC      (HEADS * OUT_CH)   // 256
#define NEG_SLOPE 0.2f
#define NBLK_NODES 196             // ceil(50000/256)

#define GT_M    64                 // nodes per gemm block
#define W_COLS  272                // 256 xt cols + 8 logit cols + 8 pad
#define W_LD    280                // Ws smem leading dim (halves)
#define XA_LD   72                 // x tile leading dim (halves)
#define GEMM_THREADS 288           // 9 warps
#define NBLK_GEMM ((N_NODES + GT_M - 1) / GT_M)                 // 782
#define NBLK_PREP ((64 * W_COLS + 255) / 256)                   // 68
#define NBLK_CNT  ((N_EDGES / 4 + 255) / 256)                   // 782
#define NBLK_SCAT ((N_EDGES / 8 + GEMM_THREADS - 1) / GEMM_THREADS)  // 348

// ---------------- device scratch (zero-initialized at load; self-cleaned) -----
__device__ __align__(16) __half2 g_xth[(size_t)N_NODES * (HC / 2)]; // [N,128] fp16x2
__device__ __align__(16) __half  g_Wh[64 * W_COLS];                 // W'' fp16
__device__ __align__(16) float g_asrc[N_NODES * HEADS];
__device__ __align__(16) float g_adst[N_NODES * HEADS];
__device__ __align__(16) float4 g_w[N_EDGES];      // per-edge softmax numerators
__device__ int   g_count[N_NODES];                 // zeroed by agg (prev run)
__device__ int   g_offs[N_NODES];
__device__ int   g_cursor[N_NODES];
__device__ int   g_esrc[N_EDGES];
__device__ unsigned long long g_state[NBLK_NODES]; // zeroed by agg (prev run)

__device__ __forceinline__ float leaky(float v) {
    return (v > 0.0f) ? v : NEG_SLOPE * v;
}

// ---------------- K1 (fused): W'' build blocks + degree-count blocks ----------
// blocks [0, NBLK_PREP): build fp16 W'' = [W | W@Vsrc | W@Vdst | 0]
// blocks [NBLK_PREP, NBLK_PREP+NBLK_CNT): degree count (g_count pre-zeroed by
// the previous run's agg_kernel; statically zero on the very first run).
__global__ void prep_count_kernel(const float* __restrict__ W,
                                  const float* __restrict__ att_src,
                                  const float* __restrict__ att_dst,
                                  const int* __restrict__ ei) {
    if (blockIdx.x >= NBLK_PREP) {
        int i = (blockIdx.x - NBLK_PREP) * 256 + threadIdx.x;
        if (i < N_EDGES / 4) {
            int4 d = __ldg((const int4*)(ei + N_EDGES) + i);
            atomicAdd(&g_count[d.x], 1);
            atomicAdd(&g_count[d.y], 1);
            atomicAdd(&g_count[d.z], 1);
            atomicAdd(&g_count[d.w], 1);
        }
        return;
    }
    int i = blockIdx.x * 256 + threadIdx.x;
    if (i < 64 * W_COLS) {
        int k = i / W_COLS, c = i % W_COLS;
        float v;
        if (c < HC) {
            v = W[(size_t)k * HC + c];
        } else if (c < HC + 8) {
            int h = (c - HC) & 3;
            const float* av = (c < HC + 4) ? att_src : att_dst;
            float s = 0.0f;
            for (int t = 0; t < OUT_CH; t++)
                s += W[(size_t)k * HC + h * OUT_CH + t] * av[h * OUT_CH + t];
            v = s;
        } else {
            v = 0.0f;
        }
        g_Wh[i] = __float2half(v);
    }
}

// ---------------- K2: single-pass CSR scan, central scanner -------------------
__global__ void scan_kernel() {
    __shared__ int sm[256];
    __shared__ int ag[256];
    __shared__ int s_excl;
    const int t = threadIdx.x;
    const int b = blockIdx.x;
    const int i = b * 256 + t;
    int c = (i < N_NODES) ? g_count[i] : 0;
    sm[t] = c;
    __syncthreads();
    for (int off = 1; off < 256; off <<= 1) {
        int u = (t >= off) ? sm[t - off] : 0;
        __syncthreads();
        sm[t] += u;
        __syncthreads();
    }

    if (t == 0)
        atomicExch(&g_state[b], (1ULL << 32) | (unsigned)sm[255]);
    __syncthreads();

    if (b == 0) {
        int a = 0;
        if (t < NBLK_NODES) {
            unsigned long long v;
            do { v = atomicAdd(&g_state[t], 0ULL); } while ((unsigned)(v >> 32) == 0u);
            a = (int)(unsigned)v;
        }
        ag[t] = a;
        __syncthreads();
        for (int off = 1; off < 256; off <<= 1) {
            int u = (t >= off) ? ag[t - off] : 0;
            __syncthreads();
            ag[t] += u;
            __syncthreads();
        }
        if (t < NBLK_NODES)
            atomicExch(&g_state[t], (2ULL << 32) | (unsigned)(ag[t] - a));
    }

    if (t == 0) {
        unsigned long long v;
        do { v = atomicAdd(&g_state[b], 0ULL); } while ((unsigned)(v >> 32) != 2u);
        s_excl = (int)(unsigned)v;
    }
    __syncthreads();

    if (i < N_NODES) {
        int off = s_excl + sm[t] - c;
        g_offs[i] = off;
        g_cursor[i] = off;
    }
}

// ---------------- K3 (fused): gemm blocks + scatter blocks, interleaved -------
// Every 3rd block (b%3==1, while ids remain) is a scatter block so the
// latency-bound scatter overlaps the latency-bound gemm instead of running
// serially after it. gemm id = b - (#scatter blocks before b).
__global__ void __launch_bounds__(GEMM_THREADS)
fused_gemm_scatter_kernel(const float* __restrict__ x, const int* __restrict__ ei) {
    __shared__ __align__(16) __half xa[GT_M * XA_LD];      // 9216 B
    __shared__ __align__(16) __half Ws[64 * W_LD];         // 35840 B
    __shared__ __align__(16) float  stage[9][16 * 16];     // 9216 B

    const int b = blockIdx.x;
    const bool is_scat = ((b % 3) == 1) && (b / 3 < NBLK_SCAT);

    // ---- scatter branch: index-only dst sort, 8 edges/thread ----
    if (is_scat) {
        int i = (b / 3) * GEMM_THREADS + threadIdx.x;
        if (i < N_EDGES / 8) {
            int4 sa = __ldg((const int4*)ei + 2 * i);
            int4 sb = __ldg((const int4*)ei + 2 * i + 1);
            int4 da = __ldg((const int4*)(ei + N_EDGES) + 2 * i);
            int4 db = __ldg((const int4*)(ei + N_EDGES) + 2 * i + 1);
            int p0 = atomicAdd(&g_cursor[da.x], 1);
            int p1 = atomicAdd(&g_cursor[da.y], 1);
            int p2 = atomicAdd(&g_cursor[da.z], 1);
            int p3 = atomicAdd(&g_cursor[da.w], 1);
            int p4 = atomicAdd(&g_cursor[db.x], 1);
            int p5 = atomicAdd(&g_cursor[db.y], 1);
            int p6 = atomicAdd(&g_cursor[db.z], 1);
            int p7 = atomicAdd(&g_cursor[db.w], 1);
            g_esrc[p0] = sa.x; g_esrc[p1] = sa.y; g_esrc[p2] = sa.z; g_esrc[p3] = sa.w;
            g_esrc[p4] = sb.x; g_esrc[p5] = sb.y; g_esrc[p6] = sb.z; g_esrc[p7] = sb.w;
        }
        return;
    }

    const int gid = b - min((b + 1) / 3, NBLK_SCAT);

    // ---- gemm branch ----
    const int tid  = threadIdx.x;
    const int warp = tid >> 5;
    const int lane = tid & 31;
    const int nblk = gid * GT_M;

    for (int i = tid; i < GT_M * IN_CH; i += GEMM_THREADS) {
        int n = i >> 6, k = i & 63;
        int node = nblk + n;
        xa[n * XA_LD + k] = __float2half((node < N_NODES) ? x[(size_t)node * IN_CH + k] : 0.0f);
    }
    for (int i = tid; i < 64 * (W_COLS / 8); i += GEMM_THREADS) {
        int k = i / (W_COLS / 8), c8 = i % (W_COLS / 8);
        *(uint4*)(Ws + k * W_LD + c8 * 8) = __ldg((const uint4*)(g_Wh + k * W_COLS) + c8);
    }
    __syncthreads();

    const int  ct0  = (warp < 8) ? (2 * warp) : 16;
    const bool has2 = (warp < 8);
    const int  ct1  = ct0 + 1;

    wmma::fragment<wmma::matrix_b, 16, 16, 16, __half, wmma::row_major> b0[4], b1[4];
#pragma unroll
    for (int kk = 0; kk < 4; kk++) {
        wmma::load_matrix_sync(b0[kk], Ws + (kk * 16) * W_LD + ct0 * 16, W_LD);
        if (has2) wmma::load_matrix_sync(b1[kk], Ws + (kk * 16) * W_LD + ct1 * 16, W_LD);
    }

    float* st = stage[warp];
    __half* xth = (__half*)g_xth;

    auto emit = [&](int nt, int ct, wmma::fragment<wmma::accumulator, 16, 16, 16, float>& acc) {
        wmma::store_matrix_sync(st, acc, 16, wmma::mem_row_major);
        __syncwarp();
        if (ct < 16) {
            int row = lane & 15, ch = lane >> 4;
            int node = nblk + nt * 16 + row;
            if (node < N_NODES) {
                float4 u = *(const float4*)(st + row * 16 + ch * 8);
                float4 v = *(const float4*)(st + row * 16 + ch * 8 + 4);
                __half2 h0 = __floats2half2_rn(u.x, u.y);
                __half2 h1 = __floats2half2_rn(u.z, u.w);
                __half2 h2 = __floats2half2_rn(v.x, v.y);
                __half2 h3 = __floats2half2_rn(v.z, v.w);
                uint4 o = make_uint4(*(unsigned*)&h0, *(unsigned*)&h1,
                                     *(unsigned*)&h2, *(unsigned*)&h3);
                *(uint4*)(xth + (size_t)node * HC + ct * 16 + ch * 8) = o;
            }
        } else {
            if (lane < 16) {
                int node = nblk + nt * 16 + lane;
                if (node < N_NODES) {
                    *(float4*)(g_asrc + node * 4) = *(const float4*)(st + lane * 16);
                    *(float4*)(g_adst + node * 4) = *(const float4*)(st + lane * 16 + 4);
                }
            }
        }
        __syncwarp();
    };

#pragma unroll
    for (int nt = 0; nt < 4; nt++) {
        wmma::fragment<wmma::matrix_a, 16, 16, 16, __half, wmma::row_major> af;
        wmma::fragment<wmma::accumulator, 16, 16, 16, float> acc0, acc1;
        wmma::fill_fragment(acc0, 0.0f);
        if (has2) wmma::fill_fragment(acc1, 0.0f);
#pragma unroll
        for (int kk = 0; kk < 4; kk++) {
            wmma::load_matrix_sync(af, xa + (nt * 16) * XA_LD + kk * 16, XA_LD);
            wmma::mma_sync(acc0, af, b0[kk], acc0);
            if (has2) wmma::mma_sync(acc1, af, b1[kk], acc1);
        }
        emit(nt, ct0, acc0);
        if (has2) emit(nt, ct1, acc1);
    }
}

// ---------------- K4: per-edge softmax numerators — 8 lanes per node ----------
__global__ void weight_kernel() {
    int gid  = blockIdx.x * blockDim.x + threadIdx.x;
    int i    = gid >> 3;               // node
    int sub  = gid & 7;
    if (i >= N_NODES) return;
    const int start = g_offs[i];
    const int deg   = g_count[i];
    float4 ad = *(const float4*)(g_adst + 4 * i);
    for (int e = start + sub; e < start + deg; e += 8) {
        int j = __ldg(g_esrc + e);
        float4 as = *(const float4*)(g_asrc + 4 * j);
        float4 w;
        w.x = __expf(leaky(as.x + ad.x));
        w.y = __expf(leaky(as.y + ad.y));
        w.z = __expf(leaky(as.z + ad.z));
        w.w = __expf(leaky(as.w + ad.w));
        g_w[e] = w;
    }
}

// ---------------- K5: agg + state cleanup for the next graph replay -----------
__global__ void agg_kernel(const float* __restrict__ bias,
                           const float* __restrict__ fc_w,
                           const float* __restrict__ fc_b,
                           float* __restrict__ out) {
    int i    = (blockIdx.x * blockDim.x + threadIdx.x) >> 5;
    int lane = threadIdx.x & 31;
    if (i >= N_NODES) return;

    const int h  = lane >> 3;
    const int cb = (lane & 7) * 8;
    const int start = g_offs[i];
    const int deg   = g_count[i];

    const float selfw = __expf(leaky(__ldg(g_asrc + 4 * i + h) + __ldg(g_adst + 4 * i + h)));
    const float* wflat = (const float*)g_w;

    float acc[8] = {0, 0, 0, 0, 0, 0, 0, 0};
    float s = 0.0f;

    auto accum = [&](float w, const uint4& v) {
        s += w;
        float2 f0 = __half22float2(*(__half2*)&v.x);
        float2 f1 = __half22float2(*(__half2*)&v.y);
        float2 f2 = __half22float2(*(__half2*)&v.z);
        float2 f3 = __half22float2(*(__half2*)&v.w);
        acc[0] += w * f0.x; acc[1] += w * f0.y;
        acc[2] += w * f1.x; acc[3] += w * f1.y;
        acc[4] += w * f2.x; acc[5] += w * f2.y;
        acc[6] += w * f3.x; acc[7] += w * f3.y;
    };

    const int total = deg + 1;   // edges + self-loop
    int e = 0;
    for (; e + 1 < total; e += 2) {
        int   ja = (e     < deg) ? __ldg(g_esrc + start + e)     : i;
        int   jb = (e + 1 < deg) ? __ldg(g_esrc + start + e + 1) : i;
        float wa = (e     < deg) ? __ldg(wflat + 4 * (start + e) + h)     : selfw;
        float wb = (e + 1 < deg) ? __ldg(wflat + 4 * (start + e + 1) + h) : selfw;
        uint4 va = __ldg((const uint4*)(g_xth + (size_t)ja * (HC / 2)) + lane);
        uint4 vb = __ldg((const uint4*)(g_xth + (size_t)jb * (HC / 2)) + lane);
        accum(wa, va);
        accum(wb, vb);
    }
    if (e < total) {
        int   j = (e < deg) ? __ldg(g_esrc + start + e) : i;
        float w = (e < deg) ? __ldg(wflat + 4 * (start + e) + h) : selfw;
        uint4 v = __ldg((const uint4*)(g_xth + (size_t)j * (HC / 2)) + lane);
        accum(w, v);
    }

    float inv = 0.25f / s;
#pragma unroll
    for (int c = 0; c < 8; c++) acc[c] *= inv;
#pragma unroll
    for (int c = 0; c < 8; c++) {
        acc[c] += __shfl_xor_sync(0xFFFFFFFFu, acc[c], 8);
        acc[c] += __shfl_xor_sync(0xFFFFFFFFu, acc[c], 16);
    }

    float4 b0 = __ldg((const float4*)(bias + cb));
    float4 b1 = __ldg((const float4*)(bias + cb + 4));
    float4 f0 = __ldg((const float4*)(fc_w + cb));
    float4 f1 = __ldg((const float4*)(fc_w + cb + 4));

    float p = fmaxf(acc[0] + b0.x, 0.0f) * f0.x
            + fmaxf(acc[1] + b0.y, 0.0f) * f0.y
            + fmaxf(acc[2] + b0.z, 0.0f) * f0.z
            + fmaxf(acc[3] + b0.w, 0.0f) * f0.w
            + fmaxf(acc[4] + b1.x, 0.0f) * f1.x
            + fmaxf(acc[5] + b1.y, 0.0f) * f1.y
            + fmaxf(acc[6] + b1.z, 0.0f) * f1.z
            + fmaxf(acc[7] + b1.w, 0.0f) * f1.w;

    p += __shfl_down_sync(0xFFFFFFFFu, p, 4, 8);
    p += __shfl_down_sync(0xFFFFFFFFu, p, 2, 8);
    p += __shfl_down_sync(0xFFFFFFFFu, p, 1, 8);

    if (lane == 0) out[i] = p + __ldg(fc_b);

    // self-clean for the next replay (deg already consumed above)
    if (lane == 0) g_count[i] = 0;
    if (lane == 1 && i < NBLK_NODES) g_state[i] = 0ULL;
}

// ---------------- launch (5 kernels) ----------------
extern "C" void kernel_launch(void* const* d_in, const int* in_sizes, int n_in,
                              void* d_out, int out_size) {
    const float* x        = (const float*)d_in[0];
    const int*   ei       = (const int*)d_in[1];     // int32 [2, E]
    const float* W        = (const float*)d_in[2];
    const float* att_src  = (const float*)d_in[3];
    const float* att_dst  = (const float*)d_in[4];
    const float* bias     = (const float*)d_in[5];
    const float* fc_w     = (const float*)d_in[6];
    const float* fc_b     = (const float*)d_in[7];
    float*       out      = (float*)d_out;

    (void)in_sizes; (void)n_in; (void)out_size;

    prep_count_kernel<<<NBLK_PREP + NBLK_CNT, 256>>>(W, att_src, att_dst, ei);
    scan_kernel<<<NBLK_NODES, 256>>>();
    fused_gemm_scatter_kernel<<<NBLK_GEMM + NBLK_SCAT, GEMM_THREADS>>>(x, ei);
    weight_kernel<<<(N_NODES * 8 + 255) / 256, 256>>>();
    agg_kernel<<<(N_NODES * 32 + 255) / 256, 256>>>(bias, fc_w, fc_b, out);
}

// round 17
// speedup vs baseline: 1.2555x; 1.1294x over previous
#include <cuda_runtime.h>
#include <cuda_fp16.h>
#include <mma.h>
#include <math_constants.h>

using namespace nvcuda;

#define N_NODES 50000
#define N_EDGES 800000
#define IN_CH   64
#define HEADS   4
#define OUT_CH  64
#define HC      (HEADS * OUT_CH)   // 256
#define NEG_SLOPE 0.2f
#define NBLK_NODES 196             // ceil(50000/256)

#define GT_M    64                 // nodes per gemm block
#define W_COLS  272                // 256 xt cols + 8 logit cols + 8 pad
#define W_LD    280                // Ws smem leading dim (halves)
#define XA_LD   72                 // x tile leading dim (halves)
#define GEMM_THREADS 288           // 9 warps
#define NBLK_GEMM ((N_NODES + GT_M - 1) / GT_M)                 // 782
#define NBLK_PREP ((64 * W_COLS + 255) / 256)                   // 68
#define NBLK_CNT  ((N_EDGES / 4 + 255) / 256)                   // 782
#define NBLK_SCAT ((N_EDGES / 8 + GEMM_THREADS - 1) / GEMM_THREADS)  // 348

// ---------------- device scratch (zero-initialized at load; self-cleaned) -----
__device__ __align__(16) __half2 g_xth[(size_t)N_NODES * (HC / 2)]; // [N,128] fp16x2
__device__ __align__(16) __half  g_Wh[64 * W_COLS];                 // W'' fp16
__device__ __align__(16) float g_asrc[N_NODES * HEADS];
__device__ __align__(16) float g_adst[N_NODES * HEADS];
__device__ int   g_count[N_NODES];                 // zeroed by agg (prev run)
__device__ int   g_offs[N_NODES];
__device__ int   g_cursor[N_NODES];
__device__ int   g_esrc[N_EDGES];
__device__ unsigned long long g_state[NBLK_NODES]; // zeroed by agg (prev run)

__device__ __forceinline__ float leaky(float v) {
    return (v > 0.0f) ? v : NEG_SLOPE * v;
}

// ---------------- K1 (fused): W'' build blocks + degree-count blocks ----------
__global__ void prep_count_kernel(const float* __restrict__ W,
                                  const float* __restrict__ att_src,
                                  const float* __restrict__ att_dst,
                                  const int* __restrict__ ei) {
    if (blockIdx.x >= NBLK_PREP) {
        int i = (blockIdx.x - NBLK_PREP) * 256 + threadIdx.x;
        if (i < N_EDGES / 4) {
            int4 d = __ldg((const int4*)(ei + N_EDGES) + i);
            atomicAdd(&g_count[d.x], 1);
            atomicAdd(&g_count[d.y], 1);
            atomicAdd(&g_count[d.z], 1);
            atomicAdd(&g_count[d.w], 1);
        }
        return;
    }
    int i = blockIdx.x * 256 + threadIdx.x;
    if (i < 64 * W_COLS) {
        int k = i / W_COLS, c = i % W_COLS;
        float v;
        if (c < HC) {
            v = W[(size_t)k * HC + c];
        } else if (c < HC + 8) {
            int h = (c - HC) & 3;
            const float* av = (c < HC + 4) ? att_src : att_dst;
            float s = 0.0f;
            for (int t = 0; t < OUT_CH; t++)
                s += W[(size_t)k * HC + h * OUT_CH + t] * av[h * OUT_CH + t];
            v = s;
        } else {
            v = 0.0f;
        }
        g_Wh[i] = __float2half(v);
    }
}

// ---------------- K2: single-pass CSR scan, central scanner -------------------
__global__ void scan_kernel() {
    __shared__ int sm[256];
    __shared__ int ag[256];
    __shared__ int s_excl;
    const int t = threadIdx.x;
    const int b = blockIdx.x;
    const int i = b * 256 + t;
    int c = (i < N_NODES) ? g_count[i] : 0;
    sm[t] = c;
    __syncthreads();
    for (int off = 1; off < 256; off <<= 1) {
        int u = (t >= off) ? sm[t - off] : 0;
        __syncthreads();
        sm[t] += u;
        __syncthreads();
    }

    if (t == 0)
        atomicExch(&g_state[b], (1ULL << 32) | (unsigned)sm[255]);
    __syncthreads();

    if (b == 0) {
        int a = 0;
        if (t < NBLK_NODES) {
            unsigned long long v;
            do { v = atomicAdd(&g_state[t], 0ULL); } while ((unsigned)(v >> 32) == 0u);
            a = (int)(unsigned)v;
        }
        ag[t] = a;
        __syncthreads();
        for (int off = 1; off < 256; off <<= 1) {
            int u = (t >= off) ? ag[t - off] : 0;
            __syncthreads();
            ag[t] += u;
            __syncthreads();
        }
        if (t < NBLK_NODES)
            atomicExch(&g_state[t], (2ULL << 32) | (unsigned)(ag[t] - a));
    }

    if (t == 0) {
        unsigned long long v;
        do { v = atomicAdd(&g_state[b], 0ULL); } while ((unsigned)(v >> 32) != 2u);
        s_excl = (int)(unsigned)v;
    }
    __syncthreads();

    if (i < N_NODES) {
        int off = s_excl + sm[t] - c;
        g_offs[i] = off;
        g_cursor[i] = off;
    }
}

// ---------------- K3 (fused): gemm blocks + scatter blocks, interleaved -------
__global__ void __launch_bounds__(GEMM_THREADS)
fused_gemm_scatter_kernel(const float* __restrict__ x, const int* __restrict__ ei) {
    __shared__ __align__(16) __half xa[GT_M * XA_LD];      // 9216 B
    __shared__ __align__(16) __half Ws[64 * W_LD];         // 35840 B
    __shared__ __align__(16) float  stage[9][16 * 16];     // 9216 B

    const int b = blockIdx.x;
    const bool is_scat = ((b % 3) == 1) && (b / 3 < NBLK_SCAT);

    // ---- scatter branch: index-only dst sort, 8 edges/thread ----
    if (is_scat) {
        int i = (b / 3) * GEMM_THREADS + threadIdx.x;
        if (i < N_EDGES / 8) {
            int4 sa = __ldg((const int4*)ei + 2 * i);
            int4 sb = __ldg((const int4*)ei + 2 * i + 1);
            int4 da = __ldg((const int4*)(ei + N_EDGES) + 2 * i);
            int4 db = __ldg((const int4*)(ei + N_EDGES) + 2 * i + 1);
            int p0 = atomicAdd(&g_cursor[da.x], 1);
            int p1 = atomicAdd(&g_cursor[da.y], 1);
            int p2 = atomicAdd(&g_cursor[da.z], 1);
            int p3 = atomicAdd(&g_cursor[da.w], 1);
            int p4 = atomicAdd(&g_cursor[db.x], 1);
            int p5 = atomicAdd(&g_cursor[db.y], 1);
            int p6 = atomicAdd(&g_cursor[db.z], 1);
            int p7 = atomicAdd(&g_cursor[db.w], 1);
            g_esrc[p0] = sa.x; g_esrc[p1] = sa.y; g_esrc[p2] = sa.z; g_esrc[p3] = sa.w;
            g_esrc[p4] = sb.x; g_esrc[p5] = sb.y; g_esrc[p6] = sb.z; g_esrc[p7] = sb.w;
        }
        return;
    }

    const int gid = b - min((b + 1) / 3, NBLK_SCAT);

    // ---- gemm branch ----
    const int tid  = threadIdx.x;
    const int warp = tid >> 5;
    const int lane = tid & 31;
    const int nblk = gid * GT_M;

    for (int i = tid; i < GT_M * IN_CH; i += GEMM_THREADS) {
        int n = i >> 6, k = i & 63;
        int node = nblk + n;
        xa[n * XA_LD + k] = __float2half((node < N_NODES) ? x[(size_t)node * IN_CH + k] : 0.0f);
    }
    for (int i = tid; i < 64 * (W_COLS / 8); i += GEMM_THREADS) {
        int k = i / (W_COLS / 8), c8 = i % (W_COLS / 8);
        *(uint4*)(Ws + k * W_LD + c8 * 8) = __ldg((const uint4*)(g_Wh + k * W_COLS) + c8);
    }
    __syncthreads();

    const int  ct0  = (warp < 8) ? (2 * warp) : 16;
    const bool has2 = (warp < 8);
    const int  ct1  = ct0 + 1;

    wmma::fragment<wmma::matrix_b, 16, 16, 16, __half, wmma::row_major> b0[4], b1[4];
#pragma unroll
    for (int kk = 0; kk < 4; kk++) {
        wmma::load_matrix_sync(b0[kk], Ws + (kk * 16) * W_LD + ct0 * 16, W_LD);
        if (has2) wmma::load_matrix_sync(b1[kk], Ws + (kk * 16) * W_LD + ct1 * 16, W_LD);
    }

    float* st = stage[warp];
    __half* xth = (__half*)g_xth;

    auto emit = [&](int nt, int ct, wmma::fragment<wmma::accumulator, 16, 16, 16, float>& acc) {
        wmma::store_matrix_sync(st, acc, 16, wmma::mem_row_major);
        __syncwarp();
        if (ct < 16) {
            int row = lane & 15, ch = lane >> 4;
            int node = nblk + nt * 16 + row;
            if (node < N_NODES) {
                float4 u = *(const float4*)(st + row * 16 + ch * 8);
                float4 v = *(const float4*)(st + row * 16 + ch * 8 + 4);
                __half2 h0 = __floats2half2_rn(u.x, u.y);
                __half2 h1 = __floats2half2_rn(u.z, u.w);
                __half2 h2 = __floats2half2_rn(v.x, v.y);
                __half2 h3 = __floats2half2_rn(v.z, v.w);
                uint4 o = make_uint4(*(unsigned*)&h0, *(unsigned*)&h1,
                                     *(unsigned*)&h2, *(unsigned*)&h3);
                *(uint4*)(xth + (size_t)node * HC + ct * 16 + ch * 8) = o;
            }
        } else {
            if (lane < 16) {
                int node = nblk + nt * 16 + lane;
                if (node < N_NODES) {
                    *(float4*)(g_asrc + node * 4) = *(const float4*)(st + lane * 16);
                    *(float4*)(g_adst + node * 4) = *(const float4*)(st + lane * 16 + 4);
                }
            }
        }
        __syncwarp();
    };

#pragma unroll
    for (int nt = 0; nt < 4; nt++) {
        wmma::fragment<wmma::matrix_a, 16, 16, 16, __half, wmma::row_major> af;
        wmma::fragment<wmma::accumulator, 16, 16, 16, float> acc0, acc1;
        wmma::fill_fragment(acc0, 0.0f);
        if (has2) wmma::fill_fragment(acc1, 0.0f);
#pragma unroll
        for (int kk = 0; kk < 4; kk++) {
            wmma::load_matrix_sync(af, xa + (nt * 16) * XA_LD + kk * 16, XA_LD);
            wmma::mma_sync(acc0, af, b0[kk], acc0);
            if (has2) wmma::mma_sync(acc1, af, b1[kk], acc1);
        }
        emit(nt, ct0, acc0);
        if (has2) emit(nt, ct1, acc1);
    }
}

// ---------------- K4: agg — inline softmax weights, pair-unrolled gathers -----
// one warp per dst node. lane owns bytes [16*lane,16*lane+16) of the 512B row:
// 8 channels of head (lane>>3), channel-in-head base cb=(lane&7)*8.
// Per pair: ALL loads (asrc_a, asrc_b, row_a, row_b) are issued before the
// exps, so MUFU latency overlaps the in-flight row gathers.
__global__ void agg_kernel(const float* __restrict__ bias,
                           const float* __restrict__ fc_w,
                           const float* __restrict__ fc_b,
                           float* __restrict__ out) {
    int i    = (blockIdx.x * blockDim.x + threadIdx.x) >> 5;
    int lane = threadIdx.x & 31;
    if (i >= N_NODES) return;

    const int h  = lane >> 3;
    const int cb = (lane & 7) * 8;
    const int start = g_offs[i];
    const int deg   = g_count[i];

    const float ad_h = __ldg(g_adst + 4 * i + h);

    float acc[8] = {0, 0, 0, 0, 0, 0, 0, 0};
    float s = 0.0f;

    auto accum = [&](float w, const uint4& v) {
        s += w;
        float2 f0 = __half22float2(*(__half2*)&v.x);
        float2 f1 = __half22float2(*(__half2*)&v.y);
        float2 f2 = __half22float2(*(__half2*)&v.z);
        float2 f3 = __half22float2(*(__half2*)&v.w);
        acc[0] += w * f0.x; acc[1] += w * f0.y;
        acc[2] += w * f1.x; acc[3] += w * f1.y;
        acc[4] += w * f2.x; acc[5] += w * f2.y;
        acc[6] += w * f3.x; acc[7] += w * f3.y;
    };

    const int total = deg + 1;   // edges + self-loop (j = i)
    int e = 0;
    for (; e + 1 < total; e += 2) {
        int ja = (e     < deg) ? __ldg(g_esrc + start + e)     : i;
        int jb = (e + 1 < deg) ? __ldg(g_esrc + start + e + 1) : i;
        // issue all four loads before any math
        float aa = __ldg(g_asrc + 4 * ja + h);
        float ab = __ldg(g_asrc + 4 * jb + h);
        uint4 va = __ldg((const uint4*)(g_xth + (size_t)ja * (HC / 2)) + lane);
        uint4 vb = __ldg((const uint4*)(g_xth + (size_t)jb * (HC / 2)) + lane);
        float wa = __expf(leaky(aa + ad_h));
        float wb = __expf(leaky(ab + ad_h));
        accum(wa, va);
        accum(wb, vb);
    }
    if (e < total) {
        int j = (e < deg) ? __ldg(g_esrc + start + e) : i;
        float a = __ldg(g_asrc + 4 * j + h);
        uint4 v = __ldg((const uint4*)(g_xth + (size_t)j * (HC / 2)) + lane);
        accum(__expf(leaky(a + ad_h)), v);
    }

    float inv = 0.25f / s;
#pragma unroll
    for (int c = 0; c < 8; c++) acc[c] *= inv;
#pragma unroll
    for (int c = 0; c < 8; c++) {
        acc[c] += __shfl_xor_sync(0xFFFFFFFFu, acc[c], 8);
        acc[c] += __shfl_xor_sync(0xFFFFFFFFu, acc[c], 16);
    }

    float4 b0 = __ldg((const float4*)(bias + cb));
    float4 b1 = __ldg((const float4*)(bias + cb + 4));
    float4 f0 = __ldg((const float4*)(fc_w + cb));
    float4 f1 = __ldg((const float4*)(fc_w + cb + 4));

    float p = fmaxf(acc[0] + b0.x, 0.0f) * f0.x
            + fmaxf(acc[1] + b0.y, 0.0f) * f0.y
            + fmaxf(acc[2] + b0.z, 0.0f) * f0.z
            + fmaxf(acc[3] + b0.w, 0.0f) * f0.w
            + fmaxf(acc[4] + b1.x, 0.0f) * f1.x
            + fmaxf(acc[5] + b1.y, 0.0f) * f1.y
            + fmaxf(acc[6] + b1.z, 0.0f) * f1.z
            + fmaxf(acc[7] + b1.w, 0.0f) * f1.w;

    p += __shfl_down_sync(0xFFFFFFFFu, p, 4, 8);
    p += __shfl_down_sync(0xFFFFFFFFu, p, 2, 8);
    p += __shfl_down_sync(0xFFFFFFFFu, p, 1, 8);

    if (lane == 0) out[i] = p + __ldg(fc_b);

    // self-clean for the next replay
    if (lane == 0) g_count[i] = 0;
    if (lane == 1 && i < NBLK_NODES) g_state[i] = 0ULL;
}

// ---------------- launch (4 kernels) ----------------
extern "C" void kernel_launch(void* const* d_in, const int* in_sizes, int n_in,
                              void* d_out, int out_size) {
    const float* x        = (const float*)d_in[0];
    const int*   ei       = (const int*)d_in[1];     // int32 [2, E]
    const float* W        = (const float*)d_in[2];
    const float* att_src  = (const float*)d_in[3];
    const float* att_dst  = (const float*)d_in[4];
    const float* bias     = (const float*)d_in[5];
    const float* fc_w     = (const float*)d_in[6];
    const float* fc_b     = (const float*)d_in[7];
    float*       out      = (float*)d_out;

    (void)in_sizes; (void)n_in; (void)out_size;

    prep_count_kernel<<<NBLK_PREP + NBLK_CNT, 256>>>(W, att_src, att_dst, ei);
    scan_kernel<<<NBLK_NODES, 256>>>();
    fused_gemm_scatter_kernel<<<NBLK_GEMM + NBLK_SCAT, GEMM_THREADS>>>(x, ei);
    agg_kernel<<<(N_NODES * 32 + 255) / 256, 256>>>(bias, fc_w, fc_b, out);
}